// round 15
// baseline (speedup 1.0000x reference)
#include <cuda_runtime.h>
#include <cstdint>

#define D 128
#define NVOX (D * D * D)
#define P 130
#define PV (P * P * P)
#define FULL 0xFFFFFFFFu
#define NSLABI 32          // ti slabs (4 i-planes each), 256 blocks per slab

// zero-padded SoA: (e0,e1,e2,state0); shell NEVER written (static zeros = pad)
__device__ float4 g_pack[PV];
__device__ int    g_cnt[NSLABI];

__device__ __forceinline__ int ld_acquire_gpu(const int* p) {
    int v;
    asm volatile("ld.acquire.gpu.global.s32 %0, [%1];" : "=r"(v) : "l"(p));
    return v;
}
__device__ __forceinline__ void red_release_gpu(int* p) {
    asm volatile("red.release.gpu.global.add.s32 [%0], 1;" :: "l"(p) : "memory");
}

__global__ void __launch_bounds__(256)
ca_fused_kernel(const float* __restrict__ x,
                const float* __restrict__ out,
                float* __restrict__ y)
{
    __shared__ __align__(16) float ly[256 * 5];   // [32 rows][40 floats]

    const int tid  = threadIdx.x;
    const int lane = tid & 31;

    // tile decode: 32 x 16 x 16 tiles of 4x8x8 (ti ascends with bid)
    const int bid = blockIdx.x;
    const int tk = bid & 15;
    const int tj = (bid >> 4) & 15;
    const int ti = bid >> 8;
    const int i0 = ti * 4, j0 = tj * 8, k0 = tk * 8;

    const int li = tid >> 6;
    const int lj = (tid >> 3) & 7;
    const int lk = tid & 7;
    const int gi = i0 + li, gj = j0 + lj, gk = k0 + lk;
    const int v  = (gi * D + gj) * D + gk;
    const int pc = ((gi + 1) * P + (gj + 1)) * P + (gk + 1);

    // ---- phase A: transpose own tile into pack (L2-coherent), keep regs ----
    const float* xv = x + (size_t)v * 5;
    float s0f = xv[0];
    float e0  = xv[1];
    float e1  = xv[2];
    float e2  = xv[3];
    __stcg(&g_pack[pc], make_float4(e0, e1, e2, s0f));

    // independent streaming loads issue while stores drain
    const float4* o4 = reinterpret_cast<const float4*>(out + (size_t)v * 8);
    float4 oa = __ldcs(o4 + 0);
    float4 ob = __ldcs(o4 + 1);

    __syncthreads();                 // whole block's stcg issued
    if (tid == 0) red_release_gpu(&g_cnt[ti]);

    // ---- local update ----
    int   state1 = 0;
    float bst    = oa.x;
    if (oa.y > bst) { bst = oa.y; state1 = 1; }
    if (oa.z > bst) { bst = oa.z; state1 = 2; }
    if (oa.w > bst) { bst = oa.w; state1 = 3; }

    int state0 = (int)s0f;
    if (state0 == 0) state1 = 0;

    float y_e0 = e0, y_e1 = e1, y_e2 = e2;
    float field1 = ob.w;
    if (state1 <= 1) {
        field1 = -1.0f;
        y_e0 = -1.0f; y_e1 = -1.0f; y_e2 = -1.0f;
    } else if (state1 == 2) {
        field1 = fminf(fmaxf(field1, 0.0f), 0.92f);
    } else {
        field1 = 1.0f;
    }

    // ---- phase B: cooperative gather (needs slabs ti-1..ti+1 complete) ----
    bool flag = (state0 <= 1) && (state1 > 1);
    unsigned mask = __ballot_sync(FULL, flag);

    if (mask) {
        if (lane == 0) {
            int lo = (ti > 0)          ? ti - 1 : ti;
            int hi = (ti < NSLABI - 1) ? ti + 1 : ti;
            for (int s = lo; s <= hi; s++) {
                while (ld_acquire_gpu(&g_cnt[s]) < 256) __nanosleep(100);
            }
        }
        __syncwarp();

        int c26 = lane + (lane >= 13 ? 1 : 0);
        int di = c26 / 9 - 1;
        int dj = (c26 / 3) % 3 - 1;
        int dk = c26 % 3 - 1;
        int noff = (di * P + dj) * P + dk;
        const bool gl = (lane < 26);

        while (mask) {
            int srcA = __ffs(mask) - 1;
            mask &= mask - 1;
            int srcB = -1;
            if (mask) { srcB = __ffs(mask) - 1; mask &= mask - 1; }

            int spcA = __shfl_sync(FULL, pc, srcA);
            int spcB = __shfl_sync(FULL, pc, srcB < 0 ? srcA : srcB);

            float4 nbA = make_float4(0.f, 0.f, 0.f, 0.f);
            float4 nbB = make_float4(0.f, 0.f, 0.f, 0.f);
            if (gl) {
                nbA = __ldcg(&g_pack[spcA + noff]);
                if (srcB >= 0) nbB = __ldcg(&g_pack[spcB + noff]);
            }

            float rxA = __shfl_sync(FULL, ob.x, srcA);
            float ryA = __shfl_sync(FULL, ob.y, srcA);
            float rzA = __shfl_sync(FULL, ob.z, srcA);
            {
                float d0 = nbA.x - rxA, d1 = nbA.y - ryA, d2 = nbA.z - rzA;
                float dist = d0 * d0 + d1 * d1 + d2 * d2;
                unsigned key = gl ? ((__float_as_uint(dist) & ~31u) | lane)
                                  : 0xFFFFFFFFu;
                unsigned kmin = __reduce_min_sync(FULL, key);
                int s = (int)(kmin & 31u);
                float w0 = __shfl_sync(FULL, nbA.x, s);
                float w1 = __shfl_sync(FULL, nbA.y, s);
                float w2 = __shfl_sync(FULL, nbA.z, s);
                if (lane == srcA) { y_e0 = w0; y_e1 = w1; y_e2 = w2; }
            }
            if (srcB >= 0) {
                float rxB = __shfl_sync(FULL, ob.x, srcB);
                float ryB = __shfl_sync(FULL, ob.y, srcB);
                float rzB = __shfl_sync(FULL, ob.z, srcB);
                float d0 = nbB.x - rxB, d1 = nbB.y - ryB, d2 = nbB.z - rzB;
                float dist = d0 * d0 + d1 * d1 + d2 * d2;
                unsigned key = gl ? ((__float_as_uint(dist) & ~31u) | lane)
                                  : 0xFFFFFFFFu;
                unsigned kmin = __reduce_min_sync(FULL, key);
                int s = (int)(kmin & 31u);
                float w0 = __shfl_sync(FULL, nbB.x, s);
                float w1 = __shfl_sync(FULL, nbB.y, s);
                float w2 = __shfl_sync(FULL, nbB.z, s);
                if (lane == srcB) { y_e0 = w0; y_e1 = w1; y_e2 = w2; }
            }
        }
    }

    // ---- stage + coalesced float4 output ----
    const int row = tid >> 3;
    ly[row * 40 + lk * 5 + 0] = (float)state1;
    ly[row * 40 + lk * 5 + 1] = y_e0;
    ly[row * 40 + lk * 5 + 2] = y_e1;
    ly[row * 40 + lk * 5 + 3] = y_e2;
    ly[row * 40 + lk * 5 + 4] = field1;
    __syncthreads();

    for (int f = tid; f < 320; f += 256) {
        int r    = f / 10;
        int part = f - r * 10;
        int ri = i0 + (r >> 3);
        int rj = j0 + (r & 7);
        long gbase = (((long)ri * D + rj) * D + k0) * 5 + part * 4;
        __stcs(reinterpret_cast<float4*>(y + gbase),
               *reinterpret_cast<const float4*>(&ly[r * 40 + part * 4]));
    }
}

extern "C" void kernel_launch(void* const* d_in, const int* in_sizes, int n_in,
                              void* d_out, int out_size)
{
    const float* x   = (const float*)d_in[0];
    const float* out = (const float*)d_in[1];
    if (n_in >= 2 && in_sizes[0] == 8 * NVOX && in_sizes[1] == 5 * NVOX) {
        const float* t = x; x = out; out = t;
    }
    float* y = (float*)d_out;

    void* cnt_addr = nullptr;
    cudaGetSymbolAddress(&cnt_addr, g_cnt);
    cudaMemsetAsync(cnt_addr, 0, NSLABI * sizeof(int));

    ca_fused_kernel<<<8192, 256>>>(x, out, y);
}

// round 17
// speedup vs baseline: 7.4666x; 7.4666x over previous
#include <cuda_runtime.h>
#include <cstdint>

#define D 128
#define NVOX (D * D * D)
#define P 130
#define PV (P * P * P)
#define FULL 0xFFFFFFFFu

// zero-padded SoA: (e0, e1, e2, state0) per voxel; shell written as zeros
__device__ float4 g_pack[PV];

// ---------- pass 1: padded transpose ----------
__global__ void __launch_bounds__(256)
transpose_kernel(const float* __restrict__ x)
{
    int pv = blockIdx.x * blockDim.x + threadIdx.x;
    if (pv >= PV) return;

    int pk = pv % P;
    int t  = pv / P;
    int pj = t % P;
    int pi = t / P;

    int i = pi - 1, j = pj - 1, k = pk - 1;
    float4 r = make_float4(0.0f, 0.0f, 0.0f, 0.0f);
    if (((unsigned)i < (unsigned)D) &
        ((unsigned)j < (unsigned)D) &
        ((unsigned)k < (unsigned)D)) {
        const float* xv = x + (((long)i * D + j) * D + k) * 5;
        r.x = xv[1];
        r.y = xv[2];
        r.z = xv[3];
        r.w = xv[0];
    }
    g_pack[pv] = r;
}

// ---------- pass 2: 4x8x8 tiles, PDL overlap, L1-resident gather ----------
__global__ void __launch_bounds__(256)
ca_update_kernel(const float* __restrict__ out, float* __restrict__ y)
{
    __shared__ __align__(16) float ly[256 * 5];   // [32 rows][40 floats]

    const int tid  = threadIdx.x;
    const int lane = tid & 31;

    // tile decode: 32 x 16 x 16 tiles of 4x8x8
    const int bid = blockIdx.x;
    const int tk = bid & 15;
    const int tj = (bid >> 4) & 15;
    const int ti = bid >> 8;
    const int i0 = ti * 4, j0 = tj * 8, k0 = tk * 8;

    const int li = tid >> 6;
    const int lj = (tid >> 3) & 7;
    const int lk = tid & 7;
    const int gi = i0 + li, gj = j0 + lj, gk = k0 + lk;
    const int v  = (gi * D + gj) * D + gk;
    const int pc = ((gi + 1) * P + (gj + 1)) * P + (gk + 1);

    // issue the streaming out-loads in the PDL overlap window,
    // while pass 1 may still be running
    const float4* o4 = reinterpret_cast<const float4*>(out + (size_t)v * 8);
    float4 oa = __ldcs(o4 + 0);
    float4 ob = __ldcs(o4 + 1);

    int   state1 = 0;
    float bst    = oa.x;
    if (oa.y > bst) { bst = oa.y; state1 = 1; }
    if (oa.z > bst) { bst = oa.z; state1 = 2; }
    if (oa.w > bst) { bst = oa.w; state1 = 3; }

    // hardware grid dependency: all of pass 1 complete before pack reads
    cudaGridDependencySynchronize();

    float4 ctr = g_pack[pc];
    int state0 = (int)ctr.w;
    if (state0 == 0) state1 = 0;

    float y_e0 = ctr.x;
    float y_e1 = ctr.y;
    float y_e2 = ctr.z;

    float field1 = ob.w;
    if (state1 <= 1) {
        field1 = -1.0f;
        y_e0 = -1.0f; y_e1 = -1.0f; y_e2 = -1.0f;
    } else if (state1 == 2) {
        field1 = fminf(fmaxf(field1, 0.0f), 0.92f);
    } else {
        field1 = 1.0f;
    }

    // warp-cooperative 26-neighbor argmin, MLP-2, tile gathers L1-resident
    bool flag = (state0 <= 1) && (state1 > 1);
    unsigned mask = __ballot_sync(FULL, flag);

    int c26 = lane + (lane >= 13 ? 1 : 0);
    int di = c26 / 9 - 1;
    int dj = (c26 / 3) % 3 - 1;
    int dk = c26 % 3 - 1;
    int noff = (di * P + dj) * P + dk;
    const bool gl = (lane < 26);

    while (mask) {
        int srcA = __ffs(mask) - 1;
        mask &= mask - 1;
        int srcB = -1;
        if (mask) { srcB = __ffs(mask) - 1; mask &= mask - 1; }

        int spcA = __shfl_sync(FULL, pc, srcA);
        int spcB = __shfl_sync(FULL, pc, srcB < 0 ? srcA : srcB);

        float4 nbA = make_float4(0.f, 0.f, 0.f, 0.f);
        float4 nbB = make_float4(0.f, 0.f, 0.f, 0.f);
        if (gl) {
            nbA = g_pack[spcA + noff];
            if (srcB >= 0) nbB = g_pack[spcB + noff];
        }

        float rxA = __shfl_sync(FULL, ob.x, srcA);
        float ryA = __shfl_sync(FULL, ob.y, srcA);
        float rzA = __shfl_sync(FULL, ob.z, srcA);
        {
            float d0 = nbA.x - rxA, d1 = nbA.y - ryA, d2 = nbA.z - rzA;
            float dist = d0 * d0 + d1 * d1 + d2 * d2;
            unsigned key = gl ? ((__float_as_uint(dist) & ~31u) | lane)
                              : 0xFFFFFFFFu;
            unsigned kmin = __reduce_min_sync(FULL, key);
            int s = (int)(kmin & 31u);
            float w0 = __shfl_sync(FULL, nbA.x, s);
            float w1 = __shfl_sync(FULL, nbA.y, s);
            float w2 = __shfl_sync(FULL, nbA.z, s);
            if (lane == srcA) { y_e0 = w0; y_e1 = w1; y_e2 = w2; }
        }
        if (srcB >= 0) {
            float rxB = __shfl_sync(FULL, ob.x, srcB);
            float ryB = __shfl_sync(FULL, ob.y, srcB);
            float rzB = __shfl_sync(FULL, ob.z, srcB);
            float d0 = nbB.x - rxB, d1 = nbB.y - ryB, d2 = nbB.z - rzB;
            float dist = d0 * d0 + d1 * d1 + d2 * d2;
            unsigned key = gl ? ((__float_as_uint(dist) & ~31u) | lane)
                              : 0xFFFFFFFFu;
            unsigned kmin = __reduce_min_sync(FULL, key);
            int s = (int)(kmin & 31u);
            float w0 = __shfl_sync(FULL, nbB.x, s);
            float w1 = __shfl_sync(FULL, nbB.y, s);
            float w2 = __shfl_sync(FULL, nbB.z, s);
            if (lane == srcB) { y_e0 = w0; y_e1 = w1; y_e2 = w2; }
        }
    }

    // stage outputs: row = li*8+lj (0..31), 40 floats per row
    const int row = tid >> 3;
    ly[row * 40 + lk * 5 + 0] = (float)state1;
    ly[row * 40 + lk * 5 + 1] = y_e0;
    ly[row * 40 + lk * 5 + 2] = y_e1;
    ly[row * 40 + lk * 5 + 3] = y_e2;
    ly[row * 40 + lk * 5 + 4] = field1;
    __syncthreads();

    // 32 rows x 10 float4; row base 16B-aligned (k0 % 8 == 0)
    for (int f = tid; f < 320; f += 256) {
        int r    = f / 10;
        int part = f - r * 10;
        int ri = i0 + (r >> 3);
        int rj = j0 + (r & 7);
        long gbase = (((long)ri * D + rj) * D + k0) * 5 + part * 4;
        __stcs(reinterpret_cast<float4*>(y + gbase),
               *reinterpret_cast<const float4*>(&ly[r * 40 + part * 4]));
    }
}

extern "C" void kernel_launch(void* const* d_in, const int* in_sizes, int n_in,
                              void* d_out, int out_size)
{
    const float* x   = (const float*)d_in[0];
    const float* out = (const float*)d_in[1];
    if (n_in >= 2 && in_sizes[0] == 8 * NVOX && in_sizes[1] == 5 * NVOX) {
        const float* t = x; x = out; out = t;
    }
    float* y = (float*)d_out;

    transpose_kernel<<<(PV + 255) / 256, 256>>>(x);

    // pass 2 with programmatic dependent launch: starts while pass 1 drains;
    // cudaGridDependencySynchronize() inside gates the g_pack reads.
    cudaLaunchConfig_t cfg = {};
    cfg.gridDim  = dim3(8192, 1, 1);
    cfg.blockDim = dim3(256, 1, 1);
    cfg.dynamicSmemBytes = 0;
    cfg.stream = 0;
    cudaLaunchAttribute attr[1];
    attr[0].id = cudaLaunchAttributeProgrammaticStreamSerialization;
    attr[0].val.programmaticStreamSerializationAllowed = 1;
    cfg.attrs = attr;
    cfg.numAttrs = 1;
    cudaError_t e = cudaLaunchKernelEx(&cfg, ca_update_kernel, out, y);
    if (e != cudaSuccess) {
        // fallback: plain serialized launch (still correct)
        ca_update_kernel<<<8192, 256>>>(out, y);
    }
}